// round 1
// baseline (speedup 1.0000x reference)
#include <cuda_runtime.h>

// ---------------- problem constants ----------------
#define N_NODES 50000
#define N_PAD   50048          // multiple of 128 (GEMM tile M)
#define E_EDGES 800000
#define R_REL   8
#define B_BASES 8
#define H_DIM   128
#define L_LAYERS 3
#define FDIM    6
#define K_TOT   (R_REL * H_DIM + H_DIM)   // 1152
#define BN_EPS  1e-5f

// ---------------- scratch (device globals; no allocations allowed) ----------
__device__ float g_x[N_PAD * H_DIM];                       // node features (residual stream)
__device__ float g_h[N_PAD * H_DIM];                       // pre-BN layer output
__device__ float g_sums[(size_t)N_PAD * R_REL * H_DIM];    // scaled per-(node,rel) segment sums
__device__ float g_Wp[K_TOT * H_DIM];                      // fused weight [R*H+H, H]
__device__ float g_invcnt[N_PAD * R_REL];
__device__ int   g_cnt[N_PAD * R_REL];
__device__ float g_chs[H_DIM];                             // channel sum   -> mu
__device__ float g_chq[H_DIM];                             // channel sumsq -> rstd

// ---------------- kernels ----------------

__global__ void k_count(const int* __restrict__ ei, const int* __restrict__ et) {
    int e = blockIdx.x * blockDim.x + threadIdx.x;
    if (e < E_EDGES) {
        int dst = ei[E_EDGES + e];
        int t   = et[e];
        atomicAdd(&g_cnt[dst * R_REL + t], 1);
    }
}

__global__ void k_invcnt() {
    int i = blockIdx.x * blockDim.x + threadIdx.x;
    if (i < N_NODES * R_REL) {
        int c = g_cnt[i];
        g_invcnt[i] = 1.0f / (float)(c > 1 ? c : 1);
    }
}

// x = emb[x_ids] + relu(node_feat @ feat_w^T + feat_b) + virtual
__global__ void k_init(const int* __restrict__ xids, const float* __restrict__ nf,
                       const float* __restrict__ emb, const float* __restrict__ fw,
                       const float* __restrict__ fb, const float* __restrict__ vrt) {
    int n = blockIdx.x;
    int h = threadIdx.x;
    __shared__ float f[FDIM];
    if (h < FDIM) f[h] = nf[n * FDIM + h];
    __syncthreads();
    float acc = fb[h];
#pragma unroll
    for (int d = 0; d < FDIM; d++) acc = fmaf(f[d], fw[h * FDIM + d], acc);
    acc = fmaxf(acc, 0.0f);
    g_x[n * H_DIM + h] = emb[xids[n] * H_DIM + h] + acc + vrt[h];
}

// Wp[k][o]: k<R*H -> sum_b comp[l,r,b]*bases[l,b,i,o]  (r=k>>7, i=k&127)
//           else  -> root[l, k-R*H, o]
__global__ void k_weights(const float* __restrict__ bases, const float* __restrict__ comp,
                          const float* __restrict__ root, int l) {
    int idx = blockIdx.x * blockDim.x + threadIdx.x;
    if (idx >= K_TOT * H_DIM) return;
    int k = idx >> 7;           // / H_DIM
    int o = idx & 127;
    float v;
    if (k < R_REL * H_DIM) {
        int r = k >> 7;
        int i = k & 127;
        v = 0.0f;
        const float* cp = comp + (l * R_REL + r) * B_BASES;
#pragma unroll
        for (int b = 0; b < B_BASES; b++)
            v = fmaf(cp[b], bases[(((size_t)l * B_BASES + b) * H_DIM + i) * H_DIM + o], v);
    } else {
        int i = k - R_REL * H_DIM;
        v = root[((size_t)l * H_DIM + i) * H_DIM + o];
    }
    g_Wp[idx] = v;
}

// one warp per edge: sums[dst*R+type][:] += invcnt * x[src][:]
__global__ void k_scatter(const int* __restrict__ ei, const int* __restrict__ et) {
    int e    = (blockIdx.x * blockDim.x + threadIdx.x) >> 5;
    int lane = threadIdx.x & 31;
    if (e >= E_EDGES) return;
    int src = ei[e];
    int dst = ei[E_EDGES + e];
    int t   = et[e];
    int seg = dst * R_REL + t;
    float w = g_invcnt[seg];
    float4 v = reinterpret_cast<const float4*>(g_x + (size_t)src * H_DIM)[lane];
    v.x *= w; v.y *= w; v.z *= w; v.w *= w;
    atomicAdd(reinterpret_cast<float4*>(g_sums + (size_t)seg * H_DIM) + lane, v);
}

// h = [sums_scaled | x] @ Wp + bias ; also accumulate per-channel sum / sumsq for BN
// M = N_PAD, K = 1152, Nc = 128. 128x128 tile, BK=8, 256 threads, 8x8 per thread.
__global__ __launch_bounds__(256, 2) void k_gemm(const float* __restrict__ bias, int l) {
    __shared__ float As[8][128];
    __shared__ float Bs[8][128];
    __shared__ float bns[H_DIM];
    __shared__ float bnq[H_DIM];

    const int bm  = blockIdx.x * 128;
    const int tid = threadIdx.x;
    const int tx  = tid & 15;
    const int ty  = tid >> 4;

    // global->smem load assignments
    const int arow = tid >> 1;            // 0..127
    const int acol = (tid & 1) * 4;       // 0 or 4
    const int brow = tid >> 5;            // 0..7
    const int bcol = (tid & 31) * 4;      // 0..124

    float acc[8][8];
#pragma unroll
    for (int i = 0; i < 8; i++)
#pragma unroll
        for (int j = 0; j < 8; j++) acc[i][j] = 0.0f;

    const int grow = bm + arow;
    const size_t sums_row = (size_t)grow * (R_REL * H_DIM);
    const size_t x_row    = (size_t)grow * H_DIM;

    for (int kt = 0; kt < K_TOT; kt += 8) {
        float4 av;
        if (kt < R_REL * H_DIM)
            av = *reinterpret_cast<const float4*>(g_sums + sums_row + kt + acol);
        else
            av = *reinterpret_cast<const float4*>(g_x + x_row + (kt - R_REL * H_DIM) + acol);
        float4 bv = *reinterpret_cast<const float4*>(g_Wp + (size_t)(kt + brow) * H_DIM + bcol);

        As[acol + 0][arow] = av.x;
        As[acol + 1][arow] = av.y;
        As[acol + 2][arow] = av.z;
        As[acol + 3][arow] = av.w;
        *reinterpret_cast<float4*>(&Bs[brow][bcol]) = bv;
        __syncthreads();

#pragma unroll
        for (int k = 0; k < 8; k++) {
            float4 a0 = *reinterpret_cast<float4*>(&As[k][ty * 4]);
            float4 a1 = *reinterpret_cast<float4*>(&As[k][64 + ty * 4]);
            float4 b0 = *reinterpret_cast<float4*>(&Bs[k][tx * 4]);
            float4 b1 = *reinterpret_cast<float4*>(&Bs[k][64 + tx * 4]);
            float a[8] = {a0.x, a0.y, a0.z, a0.w, a1.x, a1.y, a1.z, a1.w};
            float b[8] = {b0.x, b0.y, b0.z, b0.w, b1.x, b1.y, b1.z, b1.w};
#pragma unroll
            for (int i = 0; i < 8; i++)
#pragma unroll
                for (int j = 0; j < 8; j++) acc[i][j] = fmaf(a[i], b[j], acc[i][j]);
        }
        __syncthreads();
    }

    // epilogue: add bias, store h, accumulate BN stats
    if (tid < H_DIM) { bns[tid] = 0.0f; bnq[tid] = 0.0f; }
    __syncthreads();

    const float* bias_l = bias + l * H_DIM;
    float bv[8];
#pragma unroll
    for (int j = 0; j < 4; j++) { bv[j] = bias_l[tx * 4 + j]; bv[4 + j] = bias_l[64 + tx * 4 + j]; }

    float colS[8], colQ[8];
#pragma unroll
    for (int j = 0; j < 8; j++) { colS[j] = 0.0f; colQ[j] = 0.0f; }

#pragma unroll
    for (int i = 0; i < 8; i++) {
        int row = bm + ((i < 4) ? (ty * 4 + i) : (64 + ty * 4 + (i - 4)));
        if (row < N_NODES) {
            float v[8];
#pragma unroll
            for (int j = 0; j < 8; j++) {
                v[j] = acc[i][j] + bv[j];
                colS[j] += v[j];
                colQ[j] += v[j] * v[j];
            }
            *reinterpret_cast<float4*>(g_h + (size_t)row * H_DIM + tx * 4) =
                make_float4(v[0], v[1], v[2], v[3]);
            *reinterpret_cast<float4*>(g_h + (size_t)row * H_DIM + 64 + tx * 4) =
                make_float4(v[4], v[5], v[6], v[7]);
        }
    }
#pragma unroll
    for (int j = 0; j < 8; j++) {
        int col = (j < 4) ? (tx * 4 + j) : (64 + tx * 4 + (j - 4));
        atomicAdd(&bns[col], colS[j]);
        atomicAdd(&bnq[col], colQ[j]);
    }
    __syncthreads();
    if (tid < H_DIM) {
        atomicAdd(&g_chs[tid], bns[tid]);
        atomicAdd(&g_chq[tid], bnq[tid]);
    }
}

__global__ void k_bnstats() {
    int c = threadIdx.x;
    float mu  = g_chs[c] * (1.0f / N_NODES);
    float var = g_chq[c] * (1.0f / N_NODES) - mu * mu;
    g_chs[c] = mu;
    g_chq[c] = rsqrtf(var + BN_EPS);
}

__global__ void k_update(const float* __restrict__ gamma, const float* __restrict__ beta,
                         int l, float* __restrict__ out, int last) {
    int n = blockIdx.x;
    int h = threadIdx.x;
    size_t idx = (size_t)n * H_DIM + h;
    float v  = g_h[idx];
    float hn = gamma[l * H_DIM + h] * (v - g_chs[h]) * g_chq[h] + beta[l * H_DIM + h];
    float nx = g_x[idx] + fmaxf(hn, 0.0f);
    g_x[idx] = nx;
    if (last) out[idx] = nx;
}

// ---------------- launch ----------------
extern "C" void kernel_launch(void* const* d_in, const int* in_sizes, int n_in,
                              void* d_out, int out_size) {
    const int*   x_ids = (const int*)  d_in[0];
    const int*   eidx  = (const int*)  d_in[1];
    const int*   etype = (const int*)  d_in[2];
    const float* nf    = (const float*)d_in[3];
    const float* emb   = (const float*)d_in[4];
    const float* fw    = (const float*)d_in[5];
    const float* fb    = (const float*)d_in[6];
    const float* vrt   = (const float*)d_in[7];
    const float* bases = (const float*)d_in[8];
    const float* comp  = (const float*)d_in[9];
    const float* root  = (const float*)d_in[10];
    const float* bias  = (const float*)d_in[11];
    const float* gamma = (const float*)d_in[12];
    const float* beta  = (const float*)d_in[13];
    float* out = (float*)d_out;

    void *p_cnt, *p_sums, *p_chs, *p_chq;
    cudaGetSymbolAddress(&p_cnt,  g_cnt);
    cudaGetSymbolAddress(&p_sums, g_sums);
    cudaGetSymbolAddress(&p_chs,  g_chs);
    cudaGetSymbolAddress(&p_chq,  g_chq);

    cudaMemsetAsync(p_cnt, 0, sizeof(int) * (size_t)N_PAD * R_REL, 0);
    k_count<<<(E_EDGES + 255) / 256, 256>>>(eidx, etype);
    k_invcnt<<<(N_NODES * R_REL + 255) / 256, 256>>>();
    k_init<<<N_NODES, H_DIM>>>(x_ids, nf, emb, fw, fb, vrt);

    for (int l = 0; l < L_LAYERS; l++) {
        k_weights<<<(K_TOT * H_DIM + 255) / 256, 256>>>(bases, comp, root, l);
        cudaMemsetAsync(p_sums, 0, sizeof(float) * (size_t)N_PAD * R_REL * H_DIM, 0);
        cudaMemsetAsync(p_chs, 0, sizeof(float) * H_DIM, 0);
        cudaMemsetAsync(p_chq, 0, sizeof(float) * H_DIM, 0);
        k_scatter<<<(E_EDGES * 32 + 255) / 256, 256>>>(eidx, etype);
        k_gemm<<<N_PAD / 128, 256>>>(bias, l);
        k_bnstats<<<1, H_DIM>>>();
        k_update<<<N_NODES, H_DIM>>>(gamma, beta, l, out, l == L_LAYERS - 1);
    }
}

// round 4
// speedup vs baseline: 1.8433x; 1.8433x over previous
#include <cuda_runtime.h>
#include <cstdint>

// ---------------- problem constants ----------------
#define N_NODES 50000
#define N_PAD   50048          // multiple of 128
#define E_EDGES 800000
#define R_REL   8
#define B_BASES 8
#define H_DIM   128
#define L_LAYERS 3
#define FDIM    6
#define K_TOT   1152           // R*H + H
#define BN_EPS  1e-5f
#define KCHUNK  32
#define NCHUNKS 36             // K_TOT / KCHUNK
#define SMPAD   36             // 32 + 4 pad floats per row
#define GEMM_SMEM (4 * 128 * SMPAD * 4)   // 2 stages * (A + B) * 128 rows * 36 floats

// ---------------- scratch (device globals) ----------------
__device__ float g_A[(size_t)N_PAD * K_TOT];     // [n][0..1023]=scaled sums, [1024..1151]=x residual
__device__ float g_WT[(size_t)H_DIM * K_TOT];    // fused weight, transposed: [o][k] (tf32-rounded)
__device__ float g_h[(size_t)N_PAD * H_DIM];     // raw GEMM output (pre-BN; bias dropped, BN cancels it)
__device__ float g_invcnt[N_PAD * R_REL];
__device__ int   g_cnt[N_PAD * R_REL];
__device__ float g_chs[H_DIM];
__device__ float g_chq[H_DIM];

// ---------------- helpers ----------------
__device__ __forceinline__ void cpa16(uint32_t dst, const void* src) {
    asm volatile("cp.async.cg.shared.global [%0], [%1], 16;" :: "r"(dst), "l"(src) : "memory");
}
__device__ __forceinline__ uint32_t smem_u32(const void* p) {
    uint32_t a;
    asm("{ .reg .u64 t; cvta.to.shared.u64 t, %1; cvt.u32.u64 %0, t; }" : "=r"(a) : "l"(p));
    return a;
}
__device__ __forceinline__ float round_tf32(float x) {
    float r;
    asm("cvt.rna.tf32.f32 %0, %1;" : "=f"(r) : "f"(x));
    return r;
}
// D += A(16x8) * B(8x8), tf32 inputs (b32 regs), f32 accum
__device__ __forceinline__ void mma_tf32(float& c0, float& c1, float& c2, float& c3,
                                         uint32_t a0, uint32_t a1, uint32_t a2, uint32_t a3,
                                         uint32_t b0, uint32_t b1) {
    asm volatile("mma.sync.aligned.m16n8k8.row.col.f32.tf32.tf32.f32 "
                 "{%0,%1,%2,%3}, {%4,%5,%6,%7}, {%8,%9}, {%0,%1,%2,%3};"
                 : "+f"(c0), "+f"(c1), "+f"(c2), "+f"(c3)
                 : "r"(a0), "r"(a1), "r"(a2), "r"(a3), "r"(b0), "r"(b1));
}

// ---------------- small kernels ----------------
__global__ void k_count(const int* __restrict__ ei, const int* __restrict__ et) {
    int e = blockIdx.x * blockDim.x + threadIdx.x;
    if (e < E_EDGES) atomicAdd(&g_cnt[ei[E_EDGES + e] * R_REL + et[e]], 1);
}
__global__ void k_invcnt() {
    int i = blockIdx.x * blockDim.x + threadIdx.x;
    if (i < N_NODES * R_REL) {
        int c = g_cnt[i];
        g_invcnt[i] = 1.0f / (float)(c > 1 ? c : 1);
    }
}
__global__ void k_init(const int* __restrict__ xids, const float* __restrict__ nf,
                       const float* __restrict__ emb, const float* __restrict__ fw,
                       const float* __restrict__ fb, const float* __restrict__ vrt) {
    int n = blockIdx.x, h = threadIdx.x;
    __shared__ float f[FDIM];
    if (h < FDIM) f[h] = nf[n * FDIM + h];
    __syncthreads();
    float acc = fb[h];
#pragma unroll
    for (int d = 0; d < FDIM; d++) acc = fmaf(f[d], fw[h * FDIM + d], acc);
    g_A[(size_t)n * K_TOT + 1024 + h] = emb[(size_t)xids[n] * H_DIM + h] + fmaxf(acc, 0.0f) + vrt[h];
}
// fused transposed weight WT[o][k], rounded to tf32 (unbiased rna) for MMA accuracy
__global__ void k_weights(const float* __restrict__ bases, const float* __restrict__ comp,
                          const float* __restrict__ root, int l) {
    int k = blockIdx.x * blockDim.x + threadIdx.x;   // 0..1151
    int o = blockIdx.y;                              // 0..127
    float v;
    if (k < R_REL * H_DIM) {
        int r = k >> 7, i = k & 127;
        v = 0.0f;
        const float* cp = comp + (l * R_REL + r) * B_BASES;
#pragma unroll
        for (int b = 0; b < B_BASES; b++)
            v = fmaf(cp[b], bases[(((size_t)l * B_BASES + b) * H_DIM + i) * H_DIM + o], v);
    } else {
        v = root[((size_t)l * H_DIM + (k - 1024)) * H_DIM + o];
    }
    g_WT[(size_t)o * K_TOT + k] = round_tf32(v);
}
__global__ void k_zero() {
    size_t n = blockIdx.x;
    *reinterpret_cast<float4*>(g_A + n * K_TOT + threadIdx.x * 4) = make_float4(0, 0, 0, 0);
}
// one warp per edge: g_A[dst, t*128..] += invcnt * x[src]
__global__ void k_scatter(const int* __restrict__ ei, const int* __restrict__ et) {
    int e = (blockIdx.x * blockDim.x + threadIdx.x) >> 5;
    int lane = threadIdx.x & 31;
    if (e >= E_EDGES) return;
    int src = ei[e], dst = ei[E_EDGES + e], t = et[e];
    float w = g_invcnt[dst * R_REL + t];
    float4 v = *reinterpret_cast<const float4*>(g_A + (size_t)src * K_TOT + 1024 + lane * 4);
    v.x *= w; v.y *= w; v.z *= w; v.w *= w;
    atomicAdd(reinterpret_cast<float4*>(g_A + (size_t)dst * K_TOT + t * H_DIM) + lane, v);
}

// ---------------- tf32 mma.sync GEMM: g_h = A[N_PAD x 1152] @ WT^T -------------
// 128x128 CTA tile, 8 warps (2x4), warp tile 64x32, K streamed in 32-chunks,
// double-buffered cp.async. BN column stats fused into epilogue.
__global__ __launch_bounds__(256, 2) void k_gemm() {
    extern __shared__ float sm[];
    // layout: As[2][128][36], Bs[2][128][36]
    float* As = sm;
    float* Bs = sm + 2 * 128 * SMPAD;

    const int tid  = threadIdx.x;
    const int wid  = tid >> 5;
    const int lane = tid & 31;
    const int gID  = lane >> 2;      // groupID
    const int tg   = lane & 3;       // threadID_in_group
    const int wm   = wid & 1;        // warp m index (0..1) -> 64 rows
    const int wn   = wid >> 1;       // warp n index (0..3) -> 32 cols
    const int bm   = blockIdx.x * 128;

    // global load assignment: 4 float4 per matrix per stage per thread
    const int lrow = tid >> 2;       // 0..63
    const int lc4  = tid & 3;        // 0..3 (float4 col within 8)

    const float* aptr = g_A + (size_t)(bm + lrow) * K_TOT;
    const float* aptr2 = aptr + (size_t)64 * K_TOT;
    const float* bptr = g_WT + (size_t)lrow * K_TOT;
    const float* bptr2 = bptr + (size_t)64 * K_TOT;

    uint32_t as_base = smem_u32(As);
    uint32_t bs_base = smem_u32(Bs);

    float acc[4][4][4];
#pragma unroll
    for (int i = 0; i < 4; i++)
#pragma unroll
        for (int j = 0; j < 4; j++)
#pragma unroll
            for (int q = 0; q < 4; q++) acc[i][j][q] = 0.0f;

    // issue loads for chunk t into stage s
    auto load_chunk = [&](int t, int s) {
        uint32_t ad = as_base + (uint32_t)(s * 128 * SMPAD) * 4;
        uint32_t bd = bs_base + (uint32_t)(s * 128 * SMPAD) * 4;
        int ko = t * KCHUNK;
#pragma unroll
        for (int h = 0; h < 2; h++) {
            int c = lc4 * 4 + h * 16;
            cpa16(ad + (uint32_t)((lrow)      * SMPAD + c) * 4, aptr  + ko + c);
            cpa16(ad + (uint32_t)((lrow + 64) * SMPAD + c) * 4, aptr2 + ko + c);
            cpa16(bd + (uint32_t)((lrow)      * SMPAD + c) * 4, bptr  + ko + c);
            cpa16(bd + (uint32_t)((lrow + 64) * SMPAD + c) * 4, bptr2 + ko + c);
        }
        asm volatile("cp.async.commit_group;" ::: "memory");
    };

    load_chunk(0, 0);

    for (int t = 0; t < NCHUNKS; t++) {
        int s = t & 1;
        if (t + 1 < NCHUNKS) {
            load_chunk(t + 1, s ^ 1);
            asm volatile("cp.async.wait_group 1;" ::: "memory");
        } else {
            asm volatile("cp.async.wait_group 0;" ::: "memory");
        }
        __syncthreads();

        const float* Asb = As + s * 128 * SMPAD;
        const float* Bsb = Bs + s * 128 * SMPAD;
#pragma unroll
        for (int ks = 0; ks < 4; ks++) {
            // B fragments: b0 at (k=tg, n=gID), b1 at (k=tg+4, n=gID)
            uint32_t bf[4][2];
#pragma unroll
            for (int nt = 0; nt < 4; nt++) {
                const float* bp = Bsb + (wn * 32 + nt * 8 + gID) * SMPAD + ks * 8 + tg;
                bf[nt][0] = __float_as_uint(bp[0]);
                bf[nt][1] = __float_as_uint(bp[4]);
            }
#pragma unroll
            for (int mt = 0; mt < 4; mt++) {
                const float* ap = Asb + (wm * 64 + mt * 16 + gID) * SMPAD + ks * 8 + tg;
                uint32_t a0 = __float_as_uint(ap[0]);
                uint32_t a1 = __float_as_uint(ap[8 * SMPAD]);
                uint32_t a2 = __float_as_uint(ap[4]);
                uint32_t a3 = __float_as_uint(ap[8 * SMPAD + 4]);
#pragma unroll
                for (int nt = 0; nt < 4; nt++)
                    mma_tf32(acc[mt][nt][0], acc[mt][nt][1], acc[mt][nt][2], acc[mt][nt][3],
                             a0, a1, a2, a3, bf[nt][0], bf[nt][1]);
            }
        }
        __syncthreads();
    }

    // epilogue: store h + accumulate BN column stats from registers
    float colS[4][2], colQ[4][2];
#pragma unroll
    for (int nt = 0; nt < 4; nt++)
#pragma unroll
        for (int j = 0; j < 2; j++) { colS[nt][j] = 0.0f; colQ[nt][j] = 0.0f; }

#pragma unroll
    for (int mt = 0; mt < 4; mt++) {
        int row0 = bm + wm * 64 + mt * 16 + gID;
        int row1 = row0 + 8;
#pragma unroll
        for (int nt = 0; nt < 4; nt++) {
            int col = wn * 32 + nt * 8 + tg * 2;
            float c0 = acc[mt][nt][0], c1 = acc[mt][nt][1];
            float c2 = acc[mt][nt][2], c3 = acc[mt][nt][3];
            *reinterpret_cast<float2*>(g_h + (size_t)row0 * H_DIM + col) = make_float2(c0, c1);
            *reinterpret_cast<float2*>(g_h + (size_t)row1 * H_DIM + col) = make_float2(c2, c3);
            if (row0 < N_NODES) {
                colS[nt][0] += c0; colQ[nt][0] += c0 * c0;
                colS[nt][1] += c1; colQ[nt][1] += c1 * c1;
            }
            if (row1 < N_NODES) {
                colS[nt][0] += c2; colQ[nt][0] += c2 * c2;
                colS[nt][1] += c3; colQ[nt][1] += c3 * c3;
            }
        }
    }
    __syncthreads();
    float* bns = sm;          // reuse smem
    float* bnq = sm + 128;
    if (tid < 128) { bns[tid] = 0.0f; bnq[tid] = 0.0f; }
    __syncthreads();
#pragma unroll
    for (int nt = 0; nt < 4; nt++)
#pragma unroll
        for (int j = 0; j < 2; j++) {
            int col = wn * 32 + nt * 8 + tg * 2 + j;
            atomicAdd(&bns[col], colS[nt][j]);
            atomicAdd(&bnq[col], colQ[nt][j]);
        }
    __syncthreads();
    if (tid < 128) {
        atomicAdd(&g_chs[tid], bns[tid]);
        atomicAdd(&g_chq[tid], bnq[tid]);
    }
}

// ---------------- BN finalize + residual update ----------------
__global__ void k_bnstats() {
    int c = threadIdx.x;
    float mu  = g_chs[c] * (1.0f / N_NODES);
    float var = g_chq[c] * (1.0f / N_NODES) - mu * mu;
    g_chs[c] = mu;
    g_chq[c] = rsqrtf(var + BN_EPS);
}
__global__ void k_update(const float* __restrict__ gamma, const float* __restrict__ beta,
                         int l, float* __restrict__ out, int last) {
    int n = blockIdx.x, h = threadIdx.x;
    float v  = g_h[(size_t)n * H_DIM + h];
    float hn = gamma[l * H_DIM + h] * (v - g_chs[h]) * g_chq[h] + beta[l * H_DIM + h];
    float* xp = g_A + (size_t)n * K_TOT + 1024 + h;
    float nx = *xp + fmaxf(hn, 0.0f);
    *xp = nx;
    if (last) out[(size_t)n * H_DIM + h] = nx;
}

// ---------------- launch ----------------
extern "C" void kernel_launch(void* const* d_in, const int* in_sizes, int n_in,
                              void* d_out, int out_size) {
    const int*   x_ids = (const int*)  d_in[0];
    const int*   eidx  = (const int*)  d_in[1];
    const int*   etype = (const int*)  d_in[2];
    const float* nf    = (const float*)d_in[3];
    const float* emb   = (const float*)d_in[4];
    const float* fw    = (const float*)d_in[5];
    const float* fb    = (const float*)d_in[6];
    const float* vrt   = (const float*)d_in[7];
    const float* bases = (const float*)d_in[8];
    const float* comp  = (const float*)d_in[9];
    const float* root  = (const float*)d_in[10];
    const float* gamma = (const float*)d_in[12];
    const float* beta  = (const float*)d_in[13];
    float* out = (float*)d_out;

    cudaFuncSetAttribute(k_gemm, cudaFuncAttributeMaxDynamicSharedMemorySize, GEMM_SMEM);

    void *p_cnt, *p_chs, *p_chq;
    cudaGetSymbolAddress(&p_cnt, g_cnt);
    cudaGetSymbolAddress(&p_chs, g_chs);
    cudaGetSymbolAddress(&p_chq, g_chq);

    cudaMemsetAsync(p_cnt, 0, sizeof(int) * (size_t)N_PAD * R_REL, 0);
    k_count<<<(E_EDGES + 255) / 256, 256>>>(eidx, etype);
    k_invcnt<<<(N_NODES * R_REL + 255) / 256, 256>>>();
    k_init<<<N_NODES, H_DIM>>>(x_ids, nf, emb, fw, fb, vrt);

    for (int l = 0; l < L_LAYERS; l++) {
        k_weights<<<dim3(9, 128), 128>>>(bases, comp, root, l);
        k_zero<<<N_PAD, 256>>>();
        k_scatter<<<(E_EDGES * 32 + 255) / 256, 256>>>(eidx, etype);
        cudaMemsetAsync(p_chs, 0, sizeof(float) * H_DIM, 0);
        cudaMemsetAsync(p_chq, 0, sizeof(float) * H_DIM, 0);
        k_gemm<<<N_PAD / 128, 256, GEMM_SMEM>>>();
        k_bnstats<<<1, H_DIM>>>();
        k_update<<<N_NODES, H_DIM>>>(gamma, beta, l, out, l == L_LAYERS - 1);
    }
}